// round 3
// baseline (speedup 1.0000x reference)
#include <cuda_runtime.h>

// PolyConvFrame: x_0 = x; x_L = tanh(alphas[L]) * (Adj_norm @ x_{L-1}), L=1..3
// Adj_norm val_e = dinv[row_e] * w_e * dinv[col_e], dinv = deg>0 ? rsqrt(deg) : 0,
// deg_i = sum_{e: row_e=i} w_e.  Output [N, DEPTH+1, 64] fp32.
//
// edge_index dtype is detected at runtime (JAX default x64-disabled coerces
// int64 -> int32). All indices are clamped so a wrong guess can never produce
// a wild atomic address (error 717) — it would show up as rel_err instead.

#define N_NODE 100000
#define N_EDGE 1600000
#define D_FEAT 64
#define DEPTH  3

// Static device scratch (no allocation allowed anywhere).
__device__ float g_deg[N_NODE];
__device__ float g_val[N_EDGE];
__device__ float g_a[DEPTH + 1];
__device__ float g_hA[(size_t)N_NODE * D_FEAT];   // ping (25.6 MB)
__device__ float g_hB[(size_t)N_NODE * D_FEAT];   // pong (25.6 MB)
__device__ int   g_is64;

// ---------------------------------------------------------------------------
// Index helpers: dtype-agnostic, clamped.
// ---------------------------------------------------------------------------
__device__ __forceinline__ int clampi(int v) {
    v = v < 0 ? 0 : v;
    return v >= N_NODE ? N_NODE - 1 : v;
}
__device__ __forceinline__ int ld_row(const void* e, int i, int is64) {
    long long v = is64 ? ((const long long*)e)[i] : (long long)((const int*)e)[i];
    return clampi((int)v);
}
__device__ __forceinline__ int ld_col(const void* e, int i, int is64) {
    long long v = is64 ? ((const long long*)e)[N_EDGE + i]
                       : (long long)((const int*)e)[N_EDGE + i];
    return clampi((int)v);
}

// ---------------------------------------------------------------------------
// Probe: if edge_index read as int64 gives in-range values everywhere, it IS
// int64; otherwise it is int32. Samples stay within the first row of indices
// (byte offsets valid under both interpretations).
// ---------------------------------------------------------------------------
__global__ void k_probe(const void* eidx) {
    __shared__ int bad;
    if (threadIdx.x == 0) bad = 0;
    __syncthreads();
    const long long* p = (const long long*)eidx;
    for (int i = threadIdx.x; i < 512; i += blockDim.x) {
        long long v = p[(size_t)i * (N_EDGE / 512)];
        if (v < 0 || v >= N_NODE) bad = 1;   // benign race, any writer sets 1
    }
    __syncthreads();
    if (threadIdx.x == 0) g_is64 = bad ? 0 : 1;
}

__global__ void k_init_deg_alpha(const float* __restrict__ alphas) {
    int i = blockIdx.x * blockDim.x + threadIdx.x;
    if (i <= DEPTH) g_a[i] = tanhf(alphas[i]);
    for (int j = i; j < N_NODE; j += gridDim.x * blockDim.x) g_deg[j] = 0.0f;
}

// deg[row[e]] += w[e]
__global__ void k_degree(const void* __restrict__ eidx,
                         const float* __restrict__ w) {
    int e = blockIdx.x * blockDim.x + threadIdx.x;
    if (e >= N_EDGE) return;
    int is64 = g_is64;
    atomicAdd(&g_deg[ld_row(eidx, e, is64)], w[e]);
}

// val[e] = dinv[row] * w * dinv[col]
__global__ void k_edge_val(const void* __restrict__ eidx,
                           const float* __restrict__ w) {
    int e = blockIdx.x * blockDim.x + threadIdx.x;
    if (e >= N_EDGE) return;
    int is64 = g_is64;
    float dr = g_deg[ld_row(eidx, e, is64)];
    float dc = g_deg[ld_col(eidx, e, is64)];
    float ir = dr > 0.f ? rsqrtf(dr) : 0.f;
    float ic = dc > 0.f ? rsqrtf(dc) : 0.f;
    g_val[e] = ir * w[e] * ic;
}

// Copy x into scratch A and d_out slice 0; zero scratch B.
__global__ void k_copy_x(const float* __restrict__ x, float* __restrict__ out) {
    const int total = N_NODE * (D_FEAT / 4);   // 1.6M float4
    for (int t = blockIdx.x * blockDim.x + threadIdx.x; t < total;
         t += gridDim.x * blockDim.x) {
        int node = t >> 4;
        int q    = t & 15;
        float4 v = ((const float4*)x)[t];
        ((float4*)g_hA)[t] = v;
        ((float4*)g_hB)[t] = make_float4(0.f, 0.f, 0.f, 0.f);
        ((float4*)out)[(size_t)node * 64 + q] = v;   // slice 0
    }
}

// SpMM layer: dst[row] += a[L]*val[e] * src[col].  Thread = (edge, feat-quad).
// SRC_A=1: g_hA -> g_hB ; SRC_A=0: g_hB -> g_hA.
template <int SRC_A>
__global__ void k_spmm(const void* __restrict__ eidx, int L) {
    const float* __restrict__ src = SRC_A ? g_hA : g_hB;
    float*       __restrict__ dst = SRC_A ? g_hB : g_hA;

    long long t = blockIdx.x * (long long)blockDim.x + threadIdx.x;
    if (t >= (long long)N_EDGE * 16) return;
    int e = (int)(t >> 4);
    int j = (int)(t & 15);

    int is64 = g_is64;
    int r = ld_row(eidx, e, is64);
    int c = ld_col(eidx, e, is64);
    float wv = g_a[L] * g_val[e];

    const float4 v = ((const float4*)src)[(size_t)c * 16 + j];
    float* d = dst + (size_t)r * D_FEAT + j * 4;
    atomicAdd(d + 0, wv * v.x);
    atomicAdd(d + 1, wv * v.y);
    atomicAdd(d + 2, wv * v.z);
    atomicAdd(d + 3, wv * v.w);
}

// Copy accumulated layer (SRC_A ? g_hA : g_hB) into d_out slice L with
// coalesced stores; optionally zero the other buffer for the next layer.
template <int SRC_A>
__global__ void k_copyout(float* __restrict__ out, int L, int do_zero) {
    const float* __restrict__ src  = SRC_A ? g_hA : g_hB;
    float*       __restrict__ zero = SRC_A ? g_hB : g_hA;
    const int total = N_NODE * (D_FEAT / 4);
    for (int t = blockIdx.x * blockDim.x + threadIdx.x; t < total;
         t += gridDim.x * blockDim.x) {
        int node = t >> 4;
        int q    = t & 15;
        ((float4*)out)[(size_t)node * 64 + (size_t)L * 16 + q] =
            ((const float4*)src)[t];
        if (do_zero)
            ((float4*)zero)[t] = make_float4(0.f, 0.f, 0.f, 0.f);
    }
}

extern "C" void kernel_launch(void* const* d_in, const int* in_sizes, int n_in,
                              void* d_out, int out_size) {
    const float* x      = (const float*)d_in[0];
    const void*  eidx   = d_in[1];                 // [2, E], int32 or int64
    const float* w      = (const float*)d_in[2];
    const float* alphas = (const float*)d_in[3];
    float* out = (float*)d_out;

    const int TB = 256;
    const int EB = (N_EDGE + TB - 1) / TB;

    k_probe<<<1, 256>>>(eidx);
    k_init_deg_alpha<<<(N_NODE + TB - 1) / TB, TB>>>(alphas);
    k_degree<<<EB, TB>>>(eidx, w);
    k_edge_val<<<EB, TB>>>(eidx, w);
    k_copy_x<<<2048, TB>>>(x, out);

    const long long spmm_threads = (long long)N_EDGE * 16;
    const int SB = (int)((spmm_threads + TB - 1) / TB);

    // L=1: A->B, copy B to slice1, zero A
    k_spmm<1><<<SB, TB>>>(eidx, 1);
    k_copyout<0><<<2048, TB>>>(out, 1, 1);
    // L=2: B->A, copy A to slice2, zero B
    k_spmm<0><<<SB, TB>>>(eidx, 2);
    k_copyout<1><<<2048, TB>>>(out, 2, 1);
    // L=3: A->B, copy B to slice3
    k_spmm<1><<<SB, TB>>>(eidx, 3);
    k_copyout<0><<<2048, TB>>>(out, 3, 0);
}

// round 4
// speedup vs baseline: 1.8347x; 1.8347x over previous
#include <cuda_runtime.h>

// PolyConvFrame: x_0 = x; x_L = tanh(alphas[L]) * (Adj_norm @ x_{L-1}), L=1..3
// Adj_norm val_e = dinv[row_e] * w_e * dinv[col_e], dinv = deg>0 ? rsqrt(deg) : 0,
// deg_i = sum_{e: row_e=i} w_e.  Output [N, DEPTH+1, 64] fp32.
//
// R4 design: build CSR on device each launch (cheap, ~20us), then run each
// SpMM layer atomic-free: one warp per row, lane-owned float2 accumulators,
// coalesced 256B row gathers, single coalesced store per row into BOTH the
// ping-pong scratch (next layer's src) and d_out slice L (no copyout pass,
// no zeroing). Eliminates 307M fp32 LTS atomics that bound R3 at ~620us.

#define N_NODE 100000
#define N_EDGE 1600000
#define D_FEAT 64
#define DEPTH  3

// ---------------------------------------------------------------------------
// Static device scratch (no allocation allowed anywhere).
// ---------------------------------------------------------------------------
__device__ float g_deg[N_NODE];
__device__ int   g_cnt[N_NODE];
__device__ int   g_rowptr[N_NODE + 1];
__device__ int   g_cursor[N_NODE];
__device__ float g_val[N_EDGE];
__device__ int2  g_csr[N_EDGE];                     // {col, float_bits(val)}
__device__ float g_a[DEPTH + 1];
__device__ __align__(256) float g_hA[(size_t)N_NODE * D_FEAT];  // ping
__device__ __align__(256) float g_hB[(size_t)N_NODE * D_FEAT];  // pong
__device__ int   g_is64;

// ---------------------------------------------------------------------------
// Index helpers: dtype-agnostic (JAX x64-off coerces int64->int32), clamped
// so a wrong guess yields rel_err, never a wild address.
// ---------------------------------------------------------------------------
__device__ __forceinline__ int clampi(int v) {
    v = v < 0 ? 0 : v;
    return v >= N_NODE ? N_NODE - 1 : v;
}
__device__ __forceinline__ int ld_row(const void* e, int i, int is64) {
    long long v = is64 ? ((const long long*)e)[i] : (long long)((const int*)e)[i];
    return clampi((int)v);
}
__device__ __forceinline__ int ld_col(const void* e, int i, int is64) {
    long long v = is64 ? ((const long long*)e)[N_EDGE + i]
                       : (long long)((const int*)e)[N_EDGE + i];
    return clampi((int)v);
}

// Probe: sample 512 spread values as int64; any out-of-range => data is int32.
__global__ void k_probe(const void* eidx) {
    __shared__ int bad;
    if (threadIdx.x == 0) bad = 0;
    __syncthreads();
    const long long* p = (const long long*)eidx;
    for (int i = threadIdx.x; i < 512; i += blockDim.x) {
        long long v = p[(size_t)i * (N_EDGE / 512)];
        if (v < 0 || v >= N_NODE) bad = 1;
    }
    __syncthreads();
    if (threadIdx.x == 0) g_is64 = bad ? 0 : 1;
}

__global__ void k_init(const float* __restrict__ alphas) {
    int i = blockIdx.x * blockDim.x + threadIdx.x;
    if (i <= DEPTH) g_a[i] = tanhf(alphas[i]);
    for (int j = i; j < N_NODE; j += gridDim.x * blockDim.x) {
        g_deg[j] = 0.0f;
        g_cnt[j] = 0;
    }
}

// deg[row] += w ; cnt[row] += 1
__global__ void k_degree_count(const void* __restrict__ eidx,
                               const float* __restrict__ w) {
    int e = blockIdx.x * blockDim.x + threadIdx.x;
    if (e >= N_EDGE) return;
    int r = ld_row(eidx, e, g_is64);
    atomicAdd(&g_deg[r], w[e]);
    atomicAdd(&g_cnt[r], 1);
}

// val[e] = dinv[row] * w * dinv[col]
__global__ void k_edge_val(const void* __restrict__ eidx,
                           const float* __restrict__ w) {
    int e = blockIdx.x * blockDim.x + threadIdx.x;
    if (e >= N_EDGE) return;
    int is64 = g_is64;
    float dr = g_deg[ld_row(eidx, e, is64)];
    float dc = g_deg[ld_col(eidx, e, is64)];
    float ir = dr > 0.f ? rsqrtf(dr) : 0.f;
    float ic = dc > 0.f ? rsqrtf(dc) : 0.f;
    g_val[e] = ir * w[e] * ic;
}

// Single-block exclusive scan of g_cnt -> g_rowptr (and g_cursor copy).
__global__ void k_scan() {
    __shared__ int partial[1024];
    const int tid = threadIdx.x;
    const int CH = (N_NODE + 1023) / 1024;          // 98
    int begin = tid * CH;
    int endi  = begin + CH < N_NODE ? begin + CH : N_NODE;

    int s = 0;
    for (int i = begin; i < endi; i++) s += g_cnt[i];
    partial[tid] = s;
    __syncthreads();
    for (int off = 1; off < 1024; off <<= 1) {      // Hillis-Steele inclusive
        int v = (tid >= off) ? partial[tid - off] : 0;
        __syncthreads();
        partial[tid] += v;
        __syncthreads();
    }
    int run = tid ? partial[tid - 1] : 0;           // exclusive prefix
    for (int i = begin; i < endi; i++) {
        g_rowptr[i] = run;
        g_cursor[i] = run;
        run += g_cnt[i];
    }
    if (endi == N_NODE && begin < N_NODE) g_rowptr[N_NODE] = run;
}

// Bucket edges into CSR order: csr[pos] = {col, bits(val)}.
__global__ void k_fill(const void* __restrict__ eidx) {
    int e = blockIdx.x * blockDim.x + threadIdx.x;
    if (e >= N_EDGE) return;
    int is64 = g_is64;
    int r = ld_row(eidx, e, is64);
    int c = ld_col(eidx, e, is64);
    int pos = atomicAdd(&g_cursor[r], 1);
    g_csr[pos] = make_int2(c, __float_as_int(g_val[e]));
}

// Copy x into scratch A and d_out slice 0 (no zeroing needed anywhere).
__global__ void k_copy_x(const float* __restrict__ x, float* __restrict__ out) {
    const int total = N_NODE * (D_FEAT / 4);        // 1.6M float4
    for (int t = blockIdx.x * blockDim.x + threadIdx.x; t < total;
         t += gridDim.x * blockDim.x) {
        int node = t >> 4;
        int q    = t & 15;
        float4 v = ((const float4*)x)[t];
        ((float4*)g_hA)[t] = v;
        ((float4*)out)[(size_t)node * 64 + q] = v;  // slice 0
    }
}

// Atomic-free SpMM layer: warp per row, lane owns 2 features.
// dst_row = a[L] * sum_e val_e * src[col_e]; stored to scratch AND out slice L.
template <int SRC_A>
__global__ void __launch_bounds__(256)
k_spmm_csr(float* __restrict__ out, int L) {
    const float* __restrict__ src = SRC_A ? g_hA : g_hB;
    float*       __restrict__ dst = SRC_A ? g_hB : g_hA;

    int warp = (blockIdx.x * blockDim.x + threadIdx.x) >> 5;
    if (warp >= N_NODE) return;
    int lane = threadIdx.x & 31;

    int s = g_rowptr[warp];
    int e = g_rowptr[warp + 1];
    float aL = g_a[L];

    float ax = 0.f, ay = 0.f;
    int i = s;
    #pragma unroll 1
    for (; i + 4 <= e; i += 4) {                    // 4-deep MLP for gathers
        int2 cv0 = __ldg(&g_csr[i + 0]);
        int2 cv1 = __ldg(&g_csr[i + 1]);
        int2 cv2 = __ldg(&g_csr[i + 2]);
        int2 cv3 = __ldg(&g_csr[i + 3]);
        float2 s0 = __ldg((const float2*)(src + (size_t)cv0.x * D_FEAT) + lane);
        float2 s1 = __ldg((const float2*)(src + (size_t)cv1.x * D_FEAT) + lane);
        float2 s2 = __ldg((const float2*)(src + (size_t)cv2.x * D_FEAT) + lane);
        float2 s3 = __ldg((const float2*)(src + (size_t)cv3.x * D_FEAT) + lane);
        float v0 = __int_as_float(cv0.y), v1 = __int_as_float(cv1.y);
        float v2 = __int_as_float(cv2.y), v3 = __int_as_float(cv3.y);
        ax += v0 * s0.x; ay += v0 * s0.y;
        ax += v1 * s1.x; ay += v1 * s1.y;
        ax += v2 * s2.x; ay += v2 * s2.y;
        ax += v3 * s3.x; ay += v3 * s3.y;
    }
    for (; i < e; i++) {
        int2 cv = __ldg(&g_csr[i]);
        float v = __int_as_float(cv.y);
        float2 sv = __ldg((const float2*)(src + (size_t)cv.x * D_FEAT) + lane);
        ax += v * sv.x; ay += v * sv.y;
    }
    float2 r = make_float2(aL * ax, aL * ay);
    ((float2*)(dst + (size_t)warp * D_FEAT))[lane] = r;
    ((float2*)(out + (size_t)warp * 256 + (size_t)L * D_FEAT))[lane] = r;
}

extern "C" void kernel_launch(void* const* d_in, const int* in_sizes, int n_in,
                              void* d_out, int out_size) {
    const float* x      = (const float*)d_in[0];
    const void*  eidx   = d_in[1];                  // [2, E], int32 or int64
    const float* w      = (const float*)d_in[2];
    const float* alphas = (const float*)d_in[3];
    float* out = (float*)d_out;

    const int TB = 256;
    const int EB = (N_EDGE + TB - 1) / TB;

    k_probe<<<1, 256>>>(eidx);
    k_init<<<(N_NODE + TB - 1) / TB, TB>>>(alphas);
    k_degree_count<<<EB, TB>>>(eidx, w);
    k_edge_val<<<EB, TB>>>(eidx, w);
    k_scan<<<1, 1024>>>();
    k_fill<<<EB, TB>>>(eidx);
    k_copy_x<<<2048, TB>>>(x, out);

    const int SPMM_B = (N_NODE * 32 + TB - 1) / TB; // warp per row
    k_spmm_csr<1><<<SPMM_B, TB>>>(out, 1);          // A -> B
    k_spmm_csr<0><<<SPMM_B, TB>>>(out, 2);          // B -> A
    k_spmm_csr<1><<<SPMM_B, TB>>>(out, 3);          // A -> B
}